// round 14
// baseline (speedup 1.0000x reference)
#include <cuda_runtime.h>
#include <cuda_fp16.h>
#include <mma.h>
#include <math.h>
#include <stdint.h>

using namespace nvcuda;

// ---------------- problem constants ----------------
#define S_      2048
#define HID_    2048
#define H_      16
#define D_NOPE  128
#define D_ROPE  64
#define D_V     128
#define QHEAD   192
#define QL_     1536
#define KVL_    512
#define CKV_W   576
#define KVA_PAD 768
#define QDIM    3072
#define KVDIM   4096
#define EPS_    1e-6f
#define SCALE_  0.07216878364870322f

// ---------------- scratch ----------------
__device__ __half g_x     [S_ * HID_];
__device__ __half g_wqa   [HID_ * QL_];
__device__ __half g_wqb   [QL_ * QDIM];
__device__ __half g_wkva  [HID_ * KVA_PAD];
__device__ __half g_wkvb  [KVL_ * KVDIM];
__device__ __half g_wo    [H_ * D_V * HID_];
__device__ __half g_qa    [S_ * QL_];
__device__ __half g_qn    [S_ * QL_];
__device__ float  g_ckv   [S_ * CKV_W];
__device__ __half g_cnorm [S_ * KVL_];
__device__ float  g_kpe   [S_ * D_ROPE];
__device__ __half g_q     [S_ * QDIM];
__device__ __half g_kv    [S_ * KVDIM];
__device__ __half g_Q     [H_ * S_ * QHEAD];
__device__ __half g_K     [H_ * S_ * QHEAD];
__device__ __half g_V     [H_ * D_V * S_];
__device__ __half g_attn  [S_ * (H_ * D_V)];

__device__ __forceinline__ int perm16(int c) {
    int j = c & 15;
    return (c & ~15) | (((j >> 1) & 3) << 2) | ((j >> 3) << 1) | (j & 1);
}
__device__ __forceinline__ uint32_t smem_u32(const void* p) {
    uint32_t a;
    asm("{ .reg .u64 t; cvta.to.shared.u64 t, %1; cvt.u32.u64 %0, t; }" : "=r"(a) : "l"(p));
    return a;
}
__device__ __forceinline__ void cp16(uint32_t d, const void* s) {
    asm volatile("cp.async.ca.shared.global [%0], [%1], 16;" :: "r"(d), "l"(s));
}
__device__ __forceinline__ void cp_commit() {
    asm volatile("cp.async.commit_group;" ::: "memory");
}
template<int N> __device__ __forceinline__ void cp_wait() {
    asm volatile("cp.async.wait_group %0;" :: "n"(N) : "memory");
}
__device__ __forceinline__ void mma16(float* c, uint32_t a0, uint32_t a1, uint32_t a2, uint32_t a3,
                                      uint32_t b0, uint32_t b1) {
    asm volatile(
        "mma.sync.aligned.m16n8k16.row.col.f32.f16.f16.f32 "
        "{%0,%1,%2,%3}, {%4,%5,%6,%7}, {%8,%9}, {%0,%1,%2,%3};"
        : "+f"(c[0]), "+f"(c[1]), "+f"(c[2]), "+f"(c[3])
        : "r"(a0), "r"(a1), "r"(a2), "r"(a3), "r"(b0), "r"(b1));
}
__device__ __forceinline__ uint32_t pack_h2(float lo, float hi) {
    __half2 p = __floats2half2_rn(lo, hi);
    return *reinterpret_cast<uint32_t*>(&p);
}

// ---------------- prep: fused fp16 conversion ----------------
__global__ void conv_multi_kernel(
    const float4* __restrict__ s0, __half2* __restrict__ d0, int n0,
    const float4* __restrict__ s1, __half2* __restrict__ d1, int n1,
    const float4* __restrict__ s2, __half2* __restrict__ d2, int n2,
    const float4* __restrict__ s3, __half2* __restrict__ d3, int n3,
    const float4* __restrict__ s4, __half2* __restrict__ d4, int n4,
    const float* __restrict__ kva, __half* __restrict__ wkva, int n5)
{
    int i = blockIdx.x * blockDim.x + threadIdx.x;
    int j = i;
    if (j < n0) {
        float4 v = s0[j];
        d0[2*j+0] = __floats2half2_rn(v.x, v.y); d0[2*j+1] = __floats2half2_rn(v.z, v.w);
        return;
    }
    j -= n0;
    if (j < n1) {
        float4 v = s1[j];
        d1[2*j+0] = __floats2half2_rn(v.x, v.y); d1[2*j+1] = __floats2half2_rn(v.z, v.w);
        return;
    }
    j -= n1;
    if (j < n2) {
        float4 v = s2[j];
        d2[2*j+0] = __floats2half2_rn(v.x, v.y); d2[2*j+1] = __floats2half2_rn(v.z, v.w);
        return;
    }
    j -= n2;
    if (j < n3) {
        float4 v = s3[j];
        d3[2*j+0] = __floats2half2_rn(v.x, v.y); d3[2*j+1] = __floats2half2_rn(v.z, v.w);
        return;
    }
    j -= n3;
    if (j < n4) {
        float4 v = s4[j];
        d4[2*j+0] = __floats2half2_rn(v.x, v.y); d4[2*j+1] = __floats2half2_rn(v.z, v.w);
        return;
    }
    j -= n4;
    if (j < n5) {
        int k = (4 * j) / KVA_PAD, n = (4 * j) % KVA_PAD;
        __half2 lo, hi;
        if (n < CKV_W) {
            float4 v = *reinterpret_cast<const float4*>(kva + (size_t)k * CKV_W + n);
            lo = __floats2half2_rn(v.x, v.y); hi = __floats2half2_rn(v.z, v.w);
        } else {
            lo = __floats2half2_rn(0.f, 0.f); hi = lo;
        }
        __half2* dp = reinterpret_cast<__half2*>(wkva + (size_t)k * KVA_PAD + n);
        dp[0] = lo; dp[1] = hi;
    }
}

// ---------------- pipelined fp16 GEMM, dual problem sets, optional half output ----------------
#define A_STRH 72
#define B_STRH 264
#define A_SBYT (128 * A_STRH * 2)
#define B_SBYT (64 * B_STRH * 2)
#define STG_P  (A_SBYT + B_SBYT)
#define SMEM_P (3 * STG_P)

__global__ __launch_bounds__(512, 1)
void pgemm_kernel(const __half* __restrict__ A, int lda, int K,
                  const __half* __restrict__ B, int ldb,
                  void* __restrict__ C, int ldc, int N, int ho, int nt1,
                  const __half* __restrict__ A2, int lda2, int K2,
                  const __half* __restrict__ B2, int ldb2,
                  void* __restrict__ C2, int ldc2, int N2, int ho2)
{
    int bx = blockIdx.x;
    if (bx >= nt1) {
        A = A2; lda = lda2; K = K2; B = B2; ldb = ldb2;
        C = C2; ldc = ldc2; N = N2; ho = ho2;
        bx -= nt1;
    }
    const int row0 = blockIdx.y * 128;
    const int col0 = bx * 256;
    const int nk = K / 64;

    extern __shared__ char smem[];
    const uint32_t sb = smem_u32(smem);
    const int tid = threadIdx.x;
    const int wid = tid >> 5;
    const int wm  = wid >> 3;
    const int wn  = wid & 7;

    auto issue = [&](int t) {
        const int s = t % 3;
        const int k0 = t * 64;
        uint32_t ab = sb + s * STG_P;
        #pragma unroll
        for (int i = 0; i < 2; i++) {
            int idx = i * 512 + tid;
            int r = idx >> 3, c = idx & 7;
            cp16(ab + r * (A_STRH * 2) + c * 16, A + (size_t)(row0 + r) * lda + k0 + c * 8);
        }
        uint32_t bb = sb + s * STG_P + A_SBYT;
        #pragma unroll
        for (int i = 0; i < 4; i++) {
            int idx = i * 512 + tid;
            int kr = idx >> 5, c = idx & 31;
            cp16(bb + kr * (B_STRH * 2) + c * 16, B + (size_t)(k0 + kr) * ldb + col0 + c * 8);
        }
    };

    typedef wmma::fragment<wmma::matrix_a, 16, 16, 16, __half, wmma::row_major> AFrag;
    typedef wmma::fragment<wmma::matrix_b, 16, 16, 16, __half, wmma::row_major> BFrag;
    wmma::fragment<wmma::accumulator, 16, 16, 16, float> acc[4][2];
    #pragma unroll
    for (int i = 0; i < 4; i++)
        #pragma unroll
        for (int j = 0; j < 2; j++) wmma::fill_fragment(acc[i][j], 0.0f);

    issue(0); cp_commit();
    if (nk > 1) { issue(1); cp_commit(); }

    for (int t = 0; t < nk; t++) {
        if (t + 1 < nk) cp_wait<1>(); else cp_wait<0>();
        __syncthreads();
        if (t + 2 < nk) { issue(t + 2); cp_commit(); }

        const __half* As = reinterpret_cast<const __half*>(smem + (t % 3) * STG_P);
        const __half* Bs = reinterpret_cast<const __half*>(smem + (t % 3) * STG_P + A_SBYT);

        #pragma unroll
        for (int kk = 0; kk < 4; kk++) {
            AFrag af[4];
            BFrag bf[2];
            #pragma unroll
            for (int mf = 0; mf < 4; mf++)
                wmma::load_matrix_sync(af[mf], As + (wm * 64 + mf * 16) * A_STRH + kk * 16, A_STRH);
            #pragma unroll
            for (int nf = 0; nf < 2; nf++)
                wmma::load_matrix_sync(bf[nf], Bs + (kk * 16) * B_STRH + wn * 32 + nf * 16, B_STRH);
            #pragma unroll
            for (int mf = 0; mf < 4; mf++)
                #pragma unroll
                for (int nf = 0; nf < 2; nf++)
                    wmma::mma_sync(acc[mf][nf], af[mf], bf[nf], acc[mf][nf]);
        }
    }

    if (ho) {
        __half* Ch = reinterpret_cast<__half*>(C);
        #pragma unroll
        for (int mf = 0; mf < 4; mf++) {
            int gr = row0 + wm * 64 + mf * 16;
            #pragma unroll
            for (int nf = 0; nf < 2; nf++) {
                int gc = col0 + wn * 32 + nf * 16;
                if (gc + 16 <= N) {
                    wmma::fragment<wmma::accumulator, 16, 16, 16, __half> hacc;
                    #pragma unroll
                    for (int e = 0; e < hacc.num_elements; e++)
                        hacc.x[e] = __float2half(acc[mf][nf].x[e]);
                    wmma::store_matrix_sync(Ch + (size_t)gr * ldc + gc, hacc, ldc,
                                            wmma::mem_row_major);
                }
            }
        }
    } else {
        float* Cf = reinterpret_cast<float*>(C);
        #pragma unroll
        for (int mf = 0; mf < 4; mf++) {
            int gr = row0 + wm * 64 + mf * 16;
            #pragma unroll
            for (int nf = 0; nf < 2; nf++) {
                int gc = col0 + wn * 32 + nf * 16;
                if (gc + 16 <= N)
                    wmma::store_matrix_sync(Cf + (size_t)gr * ldc + gc, acc[mf][nf], ldc,
                                            wmma::mem_row_major);
            }
        }
    }
}

// ---------------- fused RMSNorm: grid.y 0 -> q_a(half), 1 -> ckv(float) ----------------
__global__ __launch_bounds__(256)
void rms_fused_kernel(const __half* __restrict__ qa, const float* __restrict__ wq,
                      const float* __restrict__ ckv, const float* __restrict__ wkv,
                      const float* __restrict__ cosT, const float* __restrict__ sinT,
                      const int* __restrict__ pos,
                      __half* __restrict__ qn, __half* __restrict__ cnorm,
                      float* __restrict__ kpe, float* __restrict__ cache)
{
    const int s = blockIdx.x;
    const int tid = threadIdx.x;
    __shared__ float sred[256];

    if (blockIdx.y == 0) {
        const __half* x = qa + (size_t)s * QL_;
        __half*       y = qn + (size_t)s * QL_;
        float v[6];
        float local = 0.f;
        #pragma unroll
        for (int i = 0; i < 6; i++) { int c = tid + i * 256; v[i] = __half2float(x[c]); local += v[i] * v[i]; }
        sred[tid] = local; __syncthreads();
        for (int st = 128; st > 0; st >>= 1) {
            if (tid < st) sred[tid] += sred[tid + st];
            __syncthreads();
        }
        float scale = rsqrtf(sred[0] / (float)QL_ + EPS_);
        #pragma unroll
        for (int i = 0; i < 6; i++) { int c = tid + i * 256; y[c] = __float2half(v[i] * scale * wq[c]); }
    } else {
        const float* x = ckv + (size_t)s * CKV_W;
        float v[2];
        float local = 0.f;
        #pragma unroll
        for (int i = 0; i < 2; i++) { int c = tid + i * 256; v[i] = x[c]; local += v[i] * v[i]; }
        sred[tid] = local; __syncthreads();
        for (int st = 128; st > 0; st >>= 1) {
            if (tid < st) sred[tid] += sred[tid + st];
            __syncthreads();
        }
        float scale = rsqrtf(sred[0] / (float)KVL_ + EPS_);
        #pragma unroll
        for (int i = 0; i < 2; i++) {
            int c = tid + i * 256;
            float y = v[i] * scale * wkv[c];
            cnorm[(size_t)s * KVL_ + c] = __float2half(y);
            cache[(size_t)s * CKV_W + c] = y;
        }
        if (tid < D_ROPE) {
            int p = pos[s];
            const float* cr = cosT + (size_t)p * D_ROPE;
            const float* sr = sinT + (size_t)p * D_ROPE;
            const float* t  = x + KVL_;
            int i = tid;
            float val;
            if (i < 32) val = t[2 * i] * cr[i] - t[2 * i + 1] * sr[i];
            else { int i2 = i - 32; val = t[2 * i2 + 1] * cr[i] + t[2 * i2] * sr[i]; }
            kpe[(size_t)s * D_ROPE + i] = val;
            cache[(size_t)s * CKV_W + KVL_ + i] = val;
        }
    }
}

// ---------------- fused assemble Q/K (perm16) + V transpose (half inputs) ----------------
__global__ __launch_bounds__(256)
void assemble_fused_kernel(const __half* __restrict__ q, const __half* __restrict__ kv,
                           const float* __restrict__ kpe,
                           const float* __restrict__ cosT, const float* __restrict__ sinT,
                           const int* __restrict__ pos,
                           __half* __restrict__ Q, __half* __restrict__ K,
                           __half* __restrict__ V)
{
    const int s0 = blockIdx.x * 64;
    const int h  = blockIdx.y;
    const int tid = threadIdx.x;

    #pragma unroll
    for (int it = 0; it < 48; it++) {
        int idx = it * 256 + tid;
        int sl = idx / QHEAD, d = idx % QHEAD;
        int s = s0 + sl;
        const __half* qrow  = q  + (size_t)s * QDIM  + h * QHEAD;
        const __half* kvrow = kv + (size_t)s * KVDIM + h * (D_NOPE + D_V);
        const size_t off = ((size_t)h * S_ + s) * QHEAD;

        float qv;
        if (d < D_NOPE) qv = __half2float(qrow[d]);
        else {
            int p = pos[s];
            const float* cr = cosT + (size_t)p * D_ROPE;
            const float* sr = sinT + (size_t)p * D_ROPE;
            const __half* t = qrow + D_NOPE;
            int i = d - D_NOPE;
            if (i < 32) qv = __half2float(t[2 * i]) * cr[i] - __half2float(t[2 * i + 1]) * sr[i];
            else { int i2 = i - 32; qv = __half2float(t[2 * i2 + 1]) * cr[i] + __half2float(t[2 * i2]) * sr[i]; }
        }
        float kvv = (d < D_NOPE) ? __half2float(kvrow[d]) : kpe[(size_t)s * D_ROPE + (d - D_NOPE)];
        int pd = perm16(d);
        Q[off + pd] = __float2half(qv);
        K[off + pd] = __float2half(kvv);
    }

    __shared__ __half vt[64 * 136];
    #pragma unroll
    for (int i = 0; i < 32; i++) {
        int idx = i * 256 + tid;
        int sl = idx >> 7, d = idx & 127;
        vt[sl * 136 + d] = kv[(size_t)(s0 + sl) * KVDIM + h * (D_NOPE + D_V) + D_NOPE + d];
    }
    __syncthreads();
    #pragma unroll
    for (int i = 0; i < 32; i++) {
        int idx = i * 256 + tid;
        int d = idx >> 6, sl = idx & 63;
        V[((size_t)h * D_V + d) * S_ + s0 + perm16(sl)] = vt[sl * 136 + d];
    }
}

// ---------------- FA2 flash: 128 q-rows/CTA, in-register softmax ----------------
#define F3_QS_STR 200
#define F3_KS_STR 200
#define F3_VS_STR 40
#define F3_QS_OFF 0
#define F3_QS_BYTES (128 * F3_QS_STR * 2)          // 51200
#define F3_KS_OFF F3_QS_BYTES
#define F3_KS_BYTES 12800
#define F3_VS_OFF (F3_KS_OFF + 2*F3_KS_BYTES)      // 76800
#define F3_VS_BYTES 10240
#define FLASH3_SMEM (F3_VS_OFF + 2*F3_VS_BYTES)    // 97280

__global__ __launch_bounds__(256, 2)
void flash3_kernel(const __half* __restrict__ Q, const __half* __restrict__ K,
                   const __half* __restrict__ V, __half* __restrict__ attn)
{
    const int qt = blockIdx.x;
    const int h  = blockIdx.y;
    const int q0 = qt * 128;
    const int nt = 4 * qt + 4;

    extern __shared__ char sm[];
    const uint32_t sb = smem_u32(sm);

    const int tid = threadIdx.x;
    const int wid = tid >> 5;
    const int lid = tid & 31;
    const int gl  = lid >> 2;
    const int tg  = lid & 3;
    const int r0  = wid * 16 + gl;

    const __half* Qg = Q + ((size_t)h * S_ + q0) * QHEAD;
    const __half* Kg = K + (size_t)h * S_ * QHEAD;
    const __half* Vg = V + (size_t)h * D_V * S_;

    auto issueKV = [&](int t, int st) {
        const __half* kp = Kg + (size_t)t * 32 * QHEAD;
        uint32_t kd = sb + F3_KS_OFF + st * F3_KS_BYTES;
        #pragma unroll
        for (int i = 0; i < 3; i++) {
            int idx = i * 256 + tid;
            int r = idx / 24, c = idx % 24;
            cp16(kd + r * (F3_KS_STR * 2) + c * 16, kp + (size_t)r * QHEAD + c * 8);
        }
        uint32_t vd = sb + F3_VS_OFF + st * F3_VS_BYTES;
        #pragma unroll
        for (int i = 0; i < 2; i++) {
            int idx = i * 256 + tid;
            int d = idx >> 2, c = idx & 3;   // 512 copies: 128 rows x 4 x 16B
            cp16(vd + d * (F3_VS_STR * 2) + c * 16, Vg + (size_t)d * S_ + t * 32 + c * 8);
        }
    };

    // Q tile (128 rows, resident) + KV tile 0
    #pragma unroll
    for (int i = 0; i < 12; i++) {
        int idx = i * 256 + tid;
        int r = idx / 24, c = idx % 24;
        cp16(sb + F3_QS_OFF + r * (F3_QS_STR * 2) + c * 16, Qg + (size_t)r * QHEAD + c * 8);
    }
    issueKV(0, 0);
    cp_commit();

    float m0 = -1e30f, m1 = -1e30f, l0 = 0.f, l1 = 0.f;
    float oacc[16][4];
    #pragma unroll
    for (int nf = 0; nf < 16; nf++)
        #pragma unroll
        for (int c = 0; c < 4; c++) oacc[nf][c] = 0.f;

    const char* QsB = sm + F3_QS_OFF;

    for (int t = 0; t < nt; t++) {
        const int st = t & 1;
        if (t + 1 < nt) { issueKV(t + 1, st ^ 1); cp_commit(); cp_wait<1>(); }
        else            { cp_wait<0>(); }
        __syncthreads();

        // ---- S = Q K^T : 16 rows x 32 keys per warp ----
        const char* KsB = sm + F3_KS_OFF + st * F3_KS_BYTES;
        float sacc[4][4];
        #pragma unroll
        for (int nf = 0; nf < 4; nf++)
            #pragma unroll
            for (int c = 0; c < 4; c++) sacc[nf][c] = 0.f;

        #pragma unroll 4
        for (int kk = 0; kk < 12; kk++) {
            uint2 qlo = *reinterpret_cast<const uint2*>(
                QsB + (r0 * F3_QS_STR + kk * 16 + 4 * tg) * 2);
            uint2 qhi = *reinterpret_cast<const uint2*>(
                QsB + ((r0 + 8) * F3_QS_STR + kk * 16 + 4 * tg) * 2);
            #pragma unroll
            for (int nf = 0; nf < 4; nf++) {
                uint2 bb = *reinterpret_cast<const uint2*>(
                    KsB + ((nf * 8 + gl) * F3_KS_STR + kk * 16 + 4 * tg) * 2);
                mma16(sacc[nf], qlo.x, qhi.x, qlo.y, qhi.y, bb.x, bb.y);
            }
        }

        // ---- in-register online softmax ----
        const bool msk = (t >= 4 * qt);
        float mx0 = -1e30f, mx1 = -1e30f;
        #pragma unroll
        for (int nf = 0; nf < 4; nf++) {
            #pragma unroll
            for (int c = 0; c < 4; c++) {
                float val = sacc[nf][c] * SCALE_;
                if (msk) {
                    int key = t * 32 + nf * 8 + 2 * tg + (c & 1);
                    int row = q0 + r0 + ((c & 2) ? 8 : 0);
                    if (key > row) val = -1e30f;
                }
                sacc[nf][c] = val;
                if (c & 2) mx1 = fmaxf(mx1, val); else mx0 = fmaxf(mx0, val);
            }
        }
        mx0 = fmaxf(mx0, __shfl_xor_sync(0xffffffffu, mx0, 1));
        mx0 = fmaxf(mx0, __shfl_xor_sync(0xffffffffu, mx0, 2));
        mx1 = fmaxf(mx1, __shfl_xor_sync(0xffffffffu, mx1, 1));
        mx1 = fmaxf(mx1, __shfl_xor_sync(0xffffffffu, mx1, 2));

        float mn0 = fmaxf(m0, mx0), mn1 = fmaxf(m1, mx1);
        float al0 = __expf(m0 - mn0), al1 = __expf(m1 - mn1);
        m0 = mn0; m1 = mn1;

        float s0 = 0.f, s1 = 0.f;
        uint32_t pa[4][2];
        #pragma unroll
        for (int nf = 0; nf < 4; nf++) {
            float e0 = __expf(sacc[nf][0] - mn0);
            float e1 = __expf(sacc[nf][1] - mn0);
            float e2 = __expf(sacc[nf][2] - mn1);
            float e3 = __expf(sacc[nf][3] - mn1);
            s0 += e0 + e1; s1 += e2 + e3;
            pa[nf][0] = pack_h2(e0, e1);
            pa[nf][1] = pack_h2(e2, e3);
        }
        s0 += __shfl_xor_sync(0xffffffffu, s0, 1);
        s0 += __shfl_xor_sync(0xffffffffu, s0, 2);
        s1 += __shfl_xor_sync(0xffffffffu, s1, 1);
        s1 += __shfl_xor_sync(0xffffffffu, s1, 2);
        l0 = l0 * al0 + s0;
        l1 = l1 * al1 + s1;

        // ---- rescale O, then O += P V ----
        #pragma unroll
        for (int nf = 0; nf < 16; nf++) {
            oacc[nf][0] *= al0; oacc[nf][1] *= al0;
            oacc[nf][2] *= al1; oacc[nf][3] *= al1;
        }
        const char* VsB = sm + F3_VS_OFF + st * F3_VS_BYTES;
        #pragma unroll
        for (int kk2 = 0; kk2 < 2; kk2++) {
            uint32_t a0 = pa[2 * kk2][0];
            uint32_t a1 = pa[2 * kk2][1];
            uint32_t a2 = pa[2 * kk2 + 1][0];
            uint32_t a3 = pa[2 * kk2 + 1][1];
            #pragma unroll
            for (int nf = 0; nf < 16; nf++) {
                uint2 bv = *reinterpret_cast<const uint2*>(
                    VsB + ((nf * 8 + gl) * F3_VS_STR + kk2 * 16 + 4 * tg) * 2);
                mma16(oacc[nf], a0, a1, a2, a3, bv.x, bv.y);
            }
        }
        __syncthreads();
    }

    // ---- epilogue: O / l ----
    float inv0 = 1.f / l0, inv1 = 1.f / l1;
    #pragma unroll
    for (int nf = 0; nf < 16; nf++) {
        int col = h * D_V + nf * 8 + 2 * tg;
        __half2* o0 = reinterpret_cast<__half2*>(attn + (size_t)(q0 + r0) * (H_ * D_V) + col);
        __half2* o8 = reinterpret_cast<__half2*>(attn + (size_t)(q0 + r0 + 8) * (H_ * D_V) + col);
        *o0 = __floats2half2_rn(oacc[nf][0] * inv0, oacc[nf][1] * inv0);
        *o8 = __floats2half2_rn(oacc[nf][2] * inv1, oacc[nf][3] * inv1);
    }
}

// ---------------- host launch ----------------
extern "C" void kernel_launch(void* const* d_in, const int* in_sizes, int n_in,
                              void* d_out, int out_size)
{
    const float* x       = (const float*)d_in[0];
    const int*   pos     = (const int*)  d_in[2];
    const float* cosT    = (const float*)d_in[3];
    const float* sinT    = (const float*)d_in[4];
    const float* q_a_w   = (const float*)d_in[5];
    const float* q_a_ln  = (const float*)d_in[6];
    const float* q_b_w   = (const float*)d_in[7];
    const float* kv_a_w  = (const float*)d_in[8];
    const float* kv_a_ln = (const float*)d_in[9];
    const float* kv_b_w  = (const float*)d_in[10];
    const float* o_w     = (const float*)d_in[11];
    float* out = (float*)d_out;
    float* out_cache = out + (size_t)S_ * HID_;

    __half *xc, *wqa, *wqb, *wkva, *wkvb, *wo, *qa, *qn, *cnorm, *q, *kv, *Q, *K, *V, *attn;
    float *ckv, *kpe;
    cudaGetSymbolAddress((void**)&xc,     g_x);
    cudaGetSymbolAddress((void**)&wqa,    g_wqa);
    cudaGetSymbolAddress((void**)&wqb,    g_wqb);
    cudaGetSymbolAddress((void**)&wkva,   g_wkva);
    cudaGetSymbolAddress((void**)&wkvb,   g_wkvb);
    cudaGetSymbolAddress((void**)&wo,     g_wo);
    cudaGetSymbolAddress((void**)&qa,     g_qa);
    cudaGetSymbolAddress((void**)&qn,     g_qn);
    cudaGetSymbolAddress((void**)&ckv,    g_ckv);
    cudaGetSymbolAddress((void**)&cnorm,  g_cnorm);
    cudaGetSymbolAddress((void**)&kpe,    g_kpe);
    cudaGetSymbolAddress((void**)&q,      g_q);
    cudaGetSymbolAddress((void**)&kv,     g_kv);
    cudaGetSymbolAddress((void**)&Q,      g_Q);
    cudaGetSymbolAddress((void**)&K,      g_K);
    cudaGetSymbolAddress((void**)&V,      g_V);
    cudaGetSymbolAddress((void**)&attn,   g_attn);

    cudaFuncSetAttribute(pgemm_kernel,  cudaFuncAttributeMaxDynamicSharedMemorySize, SMEM_P);
    cudaFuncSetAttribute(flash3_kernel, cudaFuncAttributeMaxDynamicSharedMemorySize, FLASH3_SMEM);

    // prep: all conversions in 1 launch
    {
        int n0 = S_ * HID_ / 4, n1 = HID_ * QL_ / 4, n2 = QL_ * QDIM / 4,
            n3 = KVL_ * KVDIM / 4, n4 = H_ * D_V * HID_ / 4,
            n5 = HID_ * KVA_PAD / 4;
        int total = n0 + n1 + n2 + n3 + n4 + n5;
        conv_multi_kernel<<<(total + 255) / 256, 256>>>(
            (const float4*)x,      (__half2*)xc,   n0,
            (const float4*)q_a_w,  (__half2*)wqa,  n1,
            (const float4*)q_b_w,  (__half2*)wqb,  n2,
            (const float4*)kv_b_w, (__half2*)wkvb, n3,
            (const float4*)o_w,    (__half2*)wo,   n4,
            kv_a_w, wkva, n5);
    }

    dim3 blk5(512);

    // 1) fused: qa(half) = x@q_a_w ; ckv(float) = x@kv_a_w (padded)
    pgemm_kernel<<<dim3(9, S_/128), blk5, SMEM_P>>>(
        xc, HID_, HID_, wqa, QL_, qa, QL_, QL_, 1, 6,
        xc, HID_, HID_, wkva, KVA_PAD, ckv, CKV_W, CKV_W, 0);
    // 2) fused RMSNorms
    rms_fused_kernel<<<dim3(S_, 2), 256>>>(qa, q_a_ln, ckv, kv_a_ln, cosT, sinT, pos,
                                           qn, cnorm, kpe, out_cache);
    // 3) fused: q(half) = qn@q_b_w ; kv(half) = cnorm@kv_b_w
    pgemm_kernel<<<dim3(28, S_/128), blk5, SMEM_P>>>(
        qn, QL_, QL_, wqb, QDIM, q, QDIM, QDIM, 1, 12,
        cnorm, KVL_, KVL_, wkvb, KVDIM, kv, KVDIM, KVDIM, 1);
    // 4) fused assemble Q/K + V transpose
    assemble_fused_kernel<<<dim3(S_/64, H_), 256>>>(q, kv, kpe, cosT, sinT, pos, Q, K, V);
    // 5) FA2 flash, 128-row q tiles (single wave: 256 CTAs @ 2/SM)
    flash3_kernel<<<dim3(S_/128, H_), 256, FLASH3_SMEM>>>(Q, K, V, attn);
    // 6) out(float) = attn @ o_w
    pgemm_kernel<<<dim3(HID_/256, S_/128), blk5, SMEM_P>>>(
        attn, H_*D_V, H_*D_V, wo, HID_, out, HID_, HID_, 0, HID_/256,
        nullptr, 0, 0, nullptr, 0, nullptr, 0, 0, 0);
}

// round 15
// speedup vs baseline: 1.1781x; 1.1781x over previous
#include <cuda_runtime.h>
#include <cuda_fp16.h>
#include <mma.h>
#include <math.h>
#include <stdint.h>

using namespace nvcuda;

// ---------------- problem constants ----------------
#define S_      2048
#define HID_    2048
#define H_      16
#define D_NOPE  128
#define D_ROPE  64
#define D_V     128
#define QHEAD   192
#define QL_     1536
#define KVL_    512
#define CKV_W   576
#define KVA_PAD 768
#define QDIM    3072
#define KVDIM   4096
#define EPS_    1e-6f
#define SCALE_  0.07216878364870322f

// ---------------- scratch ----------------
__device__ __half g_x     [S_ * HID_];
__device__ __half g_wqa   [HID_ * QL_];
__device__ __half g_wqb   [QL_ * QDIM];
__device__ __half g_wkva  [HID_ * KVA_PAD];
__device__ __half g_wkvb  [KVL_ * KVDIM];
__device__ __half g_wo    [H_ * D_V * HID_];
__device__ __half g_qa    [S_ * QL_];
__device__ __half g_qn    [S_ * QL_];
__device__ float  g_ckv   [S_ * CKV_W];
__device__ __half g_cnorm [S_ * KVL_];
__device__ float  g_kpe   [S_ * D_ROPE];
__device__ __half g_q     [S_ * QDIM];
__device__ __half g_kv    [S_ * KVDIM];
__device__ __half g_Q     [H_ * S_ * QHEAD];
__device__ __half g_K     [H_ * S_ * QHEAD];
__device__ __half g_V     [H_ * D_V * S_];
__device__ __half g_attn  [S_ * (H_ * D_V)];

__device__ __forceinline__ int perm16(int c) {
    int j = c & 15;
    return (c & ~15) | (((j >> 1) & 3) << 2) | ((j >> 3) << 1) | (j & 1);
}
__device__ __forceinline__ uint32_t smem_u32(const void* p) {
    uint32_t a;
    asm("{ .reg .u64 t; cvta.to.shared.u64 t, %1; cvt.u32.u64 %0, t; }" : "=r"(a) : "l"(p));
    return a;
}
__device__ __forceinline__ void cp16(uint32_t d, const void* s) {
    asm volatile("cp.async.ca.shared.global [%0], [%1], 16;" :: "r"(d), "l"(s));
}
__device__ __forceinline__ void cp_commit() {
    asm volatile("cp.async.commit_group;" ::: "memory");
}
template<int N> __device__ __forceinline__ void cp_wait() {
    asm volatile("cp.async.wait_group %0;" :: "n"(N) : "memory");
}
__device__ __forceinline__ void mma16(float* c, uint32_t a0, uint32_t a1, uint32_t a2, uint32_t a3,
                                      uint32_t b0, uint32_t b1) {
    asm volatile(
        "mma.sync.aligned.m16n8k16.row.col.f32.f16.f16.f32 "
        "{%0,%1,%2,%3}, {%4,%5,%6,%7}, {%8,%9}, {%0,%1,%2,%3};"
        : "+f"(c[0]), "+f"(c[1]), "+f"(c[2]), "+f"(c[3])
        : "r"(a0), "r"(a1), "r"(a2), "r"(a3), "r"(b0), "r"(b1));
}
__device__ __forceinline__ uint32_t pack_h2(float lo, float hi) {
    __half2 p = __floats2half2_rn(lo, hi);
    return *reinterpret_cast<uint32_t*>(&p);
}

// ---------------- prep: fused fp16 conversion ----------------
__global__ void conv_multi_kernel(
    const float4* __restrict__ s0, __half2* __restrict__ d0, int n0,
    const float4* __restrict__ s1, __half2* __restrict__ d1, int n1,
    const float4* __restrict__ s2, __half2* __restrict__ d2, int n2,
    const float4* __restrict__ s3, __half2* __restrict__ d3, int n3,
    const float4* __restrict__ s4, __half2* __restrict__ d4, int n4,
    const float* __restrict__ kva, __half* __restrict__ wkva, int n5)
{
    int i = blockIdx.x * blockDim.x + threadIdx.x;
    int j = i;
    if (j < n0) {
        float4 v = s0[j];
        d0[2*j+0] = __floats2half2_rn(v.x, v.y); d0[2*j+1] = __floats2half2_rn(v.z, v.w);
        return;
    }
    j -= n0;
    if (j < n1) {
        float4 v = s1[j];
        d1[2*j+0] = __floats2half2_rn(v.x, v.y); d1[2*j+1] = __floats2half2_rn(v.z, v.w);
        return;
    }
    j -= n1;
    if (j < n2) {
        float4 v = s2[j];
        d2[2*j+0] = __floats2half2_rn(v.x, v.y); d2[2*j+1] = __floats2half2_rn(v.z, v.w);
        return;
    }
    j -= n2;
    if (j < n3) {
        float4 v = s3[j];
        d3[2*j+0] = __floats2half2_rn(v.x, v.y); d3[2*j+1] = __floats2half2_rn(v.z, v.w);
        return;
    }
    j -= n3;
    if (j < n4) {
        float4 v = s4[j];
        d4[2*j+0] = __floats2half2_rn(v.x, v.y); d4[2*j+1] = __floats2half2_rn(v.z, v.w);
        return;
    }
    j -= n4;
    if (j < n5) {
        int k = (4 * j) / KVA_PAD, n = (4 * j) % KVA_PAD;
        __half2 lo, hi;
        if (n < CKV_W) {
            float4 v = *reinterpret_cast<const float4*>(kva + (size_t)k * CKV_W + n);
            lo = __floats2half2_rn(v.x, v.y); hi = __floats2half2_rn(v.z, v.w);
        } else {
            lo = __floats2half2_rn(0.f, 0.f); hi = lo;
        }
        __half2* dp = reinterpret_cast<__half2*>(wkva + (size_t)k * KVA_PAD + n);
        dp[0] = lo; dp[1] = hi;
    }
}

// ---------------- pipelined fp16 GEMM, dual problem sets, optional half output ----------------
#define A_STRH 72
#define B_STRH 264
#define A_SBYT (128 * A_STRH * 2)
#define B_SBYT (64 * B_STRH * 2)
#define STG_P  (A_SBYT + B_SBYT)
#define SMEM_P (3 * STG_P)

__global__ __launch_bounds__(512, 1)
void pgemm_kernel(const __half* __restrict__ A, int lda, int K,
                  const __half* __restrict__ B, int ldb,
                  void* __restrict__ C, int ldc, int N, int ho, int nt1,
                  const __half* __restrict__ A2, int lda2, int K2,
                  const __half* __restrict__ B2, int ldb2,
                  void* __restrict__ C2, int ldc2, int N2, int ho2)
{
    int bx = blockIdx.x;
    if (bx >= nt1) {
        A = A2; lda = lda2; K = K2; B = B2; ldb = ldb2;
        C = C2; ldc = ldc2; N = N2; ho = ho2;
        bx -= nt1;
    }
    const int row0 = blockIdx.y * 128;
    const int col0 = bx * 256;
    const int nk = K / 64;

    extern __shared__ char smem[];
    const uint32_t sb = smem_u32(smem);
    const int tid = threadIdx.x;
    const int wid = tid >> 5;
    const int wm  = wid >> 3;
    const int wn  = wid & 7;

    auto issue = [&](int t) {
        const int s = t % 3;
        const int k0 = t * 64;
        uint32_t ab = sb + s * STG_P;
        #pragma unroll
        for (int i = 0; i < 2; i++) {
            int idx = i * 512 + tid;
            int r = idx >> 3, c = idx & 7;
            cp16(ab + r * (A_STRH * 2) + c * 16, A + (size_t)(row0 + r) * lda + k0 + c * 8);
        }
        uint32_t bb = sb + s * STG_P + A_SBYT;
        #pragma unroll
        for (int i = 0; i < 4; i++) {
            int idx = i * 512 + tid;
            int kr = idx >> 5, c = idx & 31;
            cp16(bb + kr * (B_STRH * 2) + c * 16, B + (size_t)(k0 + kr) * ldb + col0 + c * 8);
        }
    };

    typedef wmma::fragment<wmma::matrix_a, 16, 16, 16, __half, wmma::row_major> AFrag;
    typedef wmma::fragment<wmma::matrix_b, 16, 16, 16, __half, wmma::row_major> BFrag;
    wmma::fragment<wmma::accumulator, 16, 16, 16, float> acc[4][2];
    #pragma unroll
    for (int i = 0; i < 4; i++)
        #pragma unroll
        for (int j = 0; j < 2; j++) wmma::fill_fragment(acc[i][j], 0.0f);

    issue(0); cp_commit();
    if (nk > 1) { issue(1); cp_commit(); }

    for (int t = 0; t < nk; t++) {
        if (t + 1 < nk) cp_wait<1>(); else cp_wait<0>();
        __syncthreads();
        if (t + 2 < nk) { issue(t + 2); cp_commit(); }

        const __half* As = reinterpret_cast<const __half*>(smem + (t % 3) * STG_P);
        const __half* Bs = reinterpret_cast<const __half*>(smem + (t % 3) * STG_P + A_SBYT);

        #pragma unroll
        for (int kk = 0; kk < 4; kk++) {
            AFrag af[4];
            BFrag bf[2];
            #pragma unroll
            for (int mf = 0; mf < 4; mf++)
                wmma::load_matrix_sync(af[mf], As + (wm * 64 + mf * 16) * A_STRH + kk * 16, A_STRH);
            #pragma unroll
            for (int nf = 0; nf < 2; nf++)
                wmma::load_matrix_sync(bf[nf], Bs + (kk * 16) * B_STRH + wn * 32 + nf * 16, B_STRH);
            #pragma unroll
            for (int mf = 0; mf < 4; mf++)
                #pragma unroll
                for (int nf = 0; nf < 2; nf++)
                    wmma::mma_sync(acc[mf][nf], af[mf], bf[nf], acc[mf][nf]);
        }
    }

    if (ho) {
        __half* Ch = reinterpret_cast<__half*>(C);
        #pragma unroll
        for (int mf = 0; mf < 4; mf++) {
            int gr = row0 + wm * 64 + mf * 16;
            #pragma unroll
            for (int nf = 0; nf < 2; nf++) {
                int gc = col0 + wn * 32 + nf * 16;
                if (gc + 16 <= N) {
                    wmma::fragment<wmma::accumulator, 16, 16, 16, __half> hacc;
                    #pragma unroll
                    for (int e = 0; e < hacc.num_elements; e++)
                        hacc.x[e] = __float2half(acc[mf][nf].x[e]);
                    wmma::store_matrix_sync(Ch + (size_t)gr * ldc + gc, hacc, ldc,
                                            wmma::mem_row_major);
                }
            }
        }
    } else {
        float* Cf = reinterpret_cast<float*>(C);
        #pragma unroll
        for (int mf = 0; mf < 4; mf++) {
            int gr = row0 + wm * 64 + mf * 16;
            #pragma unroll
            for (int nf = 0; nf < 2; nf++) {
                int gc = col0 + wn * 32 + nf * 16;
                if (gc + 16 <= N)
                    wmma::store_matrix_sync(Cf + (size_t)gr * ldc + gc, acc[mf][nf], ldc,
                                            wmma::mem_row_major);
            }
        }
    }
}

// ---------------- fused RMSNorm: grid.y 0 -> q_a(half), 1 -> ckv(float) ----------------
__global__ __launch_bounds__(256)
void rms_fused_kernel(const __half* __restrict__ qa, const float* __restrict__ wq,
                      const float* __restrict__ ckv, const float* __restrict__ wkv,
                      const float* __restrict__ cosT, const float* __restrict__ sinT,
                      const int* __restrict__ pos,
                      __half* __restrict__ qn, __half* __restrict__ cnorm,
                      float* __restrict__ kpe, float* __restrict__ cache)
{
    const int s = blockIdx.x;
    const int tid = threadIdx.x;
    __shared__ float sred[256];

    if (blockIdx.y == 0) {
        const __half* x = qa + (size_t)s * QL_;
        __half*       y = qn + (size_t)s * QL_;
        float v[6];
        float local = 0.f;
        #pragma unroll
        for (int i = 0; i < 6; i++) { int c = tid + i * 256; v[i] = __half2float(x[c]); local += v[i] * v[i]; }
        sred[tid] = local; __syncthreads();
        for (int st = 128; st > 0; st >>= 1) {
            if (tid < st) sred[tid] += sred[tid + st];
            __syncthreads();
        }
        float scale = rsqrtf(sred[0] / (float)QL_ + EPS_);
        #pragma unroll
        for (int i = 0; i < 6; i++) { int c = tid + i * 256; y[c] = __float2half(v[i] * scale * wq[c]); }
    } else {
        const float* x = ckv + (size_t)s * CKV_W;
        float v[2];
        float local = 0.f;
        #pragma unroll
        for (int i = 0; i < 2; i++) { int c = tid + i * 256; v[i] = x[c]; local += v[i] * v[i]; }
        sred[tid] = local; __syncthreads();
        for (int st = 128; st > 0; st >>= 1) {
            if (tid < st) sred[tid] += sred[tid + st];
            __syncthreads();
        }
        float scale = rsqrtf(sred[0] / (float)KVL_ + EPS_);
        #pragma unroll
        for (int i = 0; i < 2; i++) {
            int c = tid + i * 256;
            float y = v[i] * scale * wkv[c];
            cnorm[(size_t)s * KVL_ + c] = __float2half(y);
            cache[(size_t)s * CKV_W + c] = y;
        }
        if (tid < D_ROPE) {
            int p = pos[s];
            const float* cr = cosT + (size_t)p * D_ROPE;
            const float* sr = sinT + (size_t)p * D_ROPE;
            const float* t  = x + KVL_;
            int i = tid;
            float val;
            if (i < 32) val = t[2 * i] * cr[i] - t[2 * i + 1] * sr[i];
            else { int i2 = i - 32; val = t[2 * i2 + 1] * cr[i] + t[2 * i2] * sr[i]; }
            kpe[(size_t)s * D_ROPE + i] = val;
            cache[(size_t)s * CKV_W + KVL_ + i] = val;
        }
    }
}

// ---------------- fused assemble Q/K (perm16) + V transpose (half inputs) ----------------
__global__ __launch_bounds__(256)
void assemble_fused_kernel(const __half* __restrict__ q, const __half* __restrict__ kv,
                           const float* __restrict__ kpe,
                           const float* __restrict__ cosT, const float* __restrict__ sinT,
                           const int* __restrict__ pos,
                           __half* __restrict__ Q, __half* __restrict__ K,
                           __half* __restrict__ V)
{
    const int s0 = blockIdx.x * 64;
    const int h  = blockIdx.y;
    const int tid = threadIdx.x;

    #pragma unroll
    for (int it = 0; it < 48; it++) {
        int idx = it * 256 + tid;
        int sl = idx / QHEAD, d = idx % QHEAD;
        int s = s0 + sl;
        const __half* qrow  = q  + (size_t)s * QDIM  + h * QHEAD;
        const __half* kvrow = kv + (size_t)s * KVDIM + h * (D_NOPE + D_V);
        const size_t off = ((size_t)h * S_ + s) * QHEAD;

        float qv;
        if (d < D_NOPE) qv = __half2float(qrow[d]);
        else {
            int p = pos[s];
            const float* cr = cosT + (size_t)p * D_ROPE;
            const float* sr = sinT + (size_t)p * D_ROPE;
            const __half* t = qrow + D_NOPE;
            int i = d - D_NOPE;
            if (i < 32) qv = __half2float(t[2 * i]) * cr[i] - __half2float(t[2 * i + 1]) * sr[i];
            else { int i2 = i - 32; qv = __half2float(t[2 * i2 + 1]) * cr[i] + __half2float(t[2 * i2]) * sr[i]; }
        }
        float kvv = (d < D_NOPE) ? __half2float(kvrow[d]) : kpe[(size_t)s * D_ROPE + (d - D_NOPE)];
        int pd = perm16(d);
        Q[off + pd] = __float2half(qv);
        K[off + pd] = __float2half(kvv);
    }

    __shared__ __half vt[64 * 136];
    #pragma unroll
    for (int i = 0; i < 32; i++) {
        int idx = i * 256 + tid;
        int sl = idx >> 7, d = idx & 127;
        vt[sl * 136 + d] = kv[(size_t)(s0 + sl) * KVDIM + h * (D_NOPE + D_V) + D_NOPE + d];
    }
    __syncthreads();
    #pragma unroll
    for (int i = 0; i < 32; i++) {
        int idx = i * 256 + tid;
        int d = idx >> 6, sl = idx & 63;
        V[((size_t)h * D_V + d) * S_ + s0 + perm16(sl)] = vt[sl * 136 + d];
    }
}

// ---------------- FA2 flash: 64 q-rows/CTA, 128 thr, 3 CTAs/SM (round-12 proven shape) ----------------
#define F2_QS_STR 200
#define F2_KS_STR 200
#define F2_VS_STR 40
#define F2_QS_OFF 0
#define F2_KS_OFF 25600
#define F2_KS_BYTES 12800
#define F2_VS_OFF (F2_KS_OFF + 2*F2_KS_BYTES)
#define F2_VS_BYTES 10240
#define FLASH2_SMEM (F2_VS_OFF + 2*F2_VS_BYTES)

__global__ __launch_bounds__(128, 3)
void flash2_kernel(const __half* __restrict__ Q, const __half* __restrict__ K,
                   const __half* __restrict__ V, __half* __restrict__ attn)
{
    const int qt = blockIdx.x;
    const int h  = blockIdx.y;
    const int q0 = qt * 64;
    const int nt = 2 * qt + 2;

    extern __shared__ char sm[];
    const uint32_t sb = smem_u32(sm);

    const int tid = threadIdx.x;
    const int wid = tid >> 5;
    const int lid = tid & 31;
    const int gl  = lid >> 2;
    const int tg  = lid & 3;
    const int r0  = wid * 16 + gl;

    const __half* Qg = Q + ((size_t)h * S_ + q0) * QHEAD;
    const __half* Kg = K + (size_t)h * S_ * QHEAD;
    const __half* Vg = V + (size_t)h * D_V * S_;

    auto issueKV = [&](int t, int st) {
        const __half* kp = Kg + (size_t)t * 32 * QHEAD;
        uint32_t kd = sb + F2_KS_OFF + st * F2_KS_BYTES;
        #pragma unroll
        for (int i = 0; i < 6; i++) {
            int idx = i * 128 + tid;
            int r = idx / 24, c = idx % 24;
            cp16(kd + r * (F2_KS_STR * 2) + c * 16, kp + (size_t)r * QHEAD + c * 8);
        }
        uint32_t vd = sb + F2_VS_OFF + st * F2_VS_BYTES;
        #pragma unroll
        for (int i = 0; i < 4; i++) {
            int idx = i * 128 + tid;
            int d = idx >> 2, c = idx & 3;
            cp16(vd + d * (F2_VS_STR * 2) + c * 16, Vg + (size_t)d * S_ + t * 32 + c * 8);
        }
    };

    #pragma unroll
    for (int i = 0; i < 12; i++) {
        int idx = i * 128 + tid;
        int r = idx / 24, c = idx % 24;
        cp16(sb + F2_QS_OFF + r * (F2_QS_STR * 2) + c * 16, Qg + (size_t)r * QHEAD + c * 8);
    }
    issueKV(0, 0);
    cp_commit();

    float m0 = -1e30f, m1 = -1e30f, l0 = 0.f, l1 = 0.f;
    float oacc[16][4];
    #pragma unroll
    for (int nf = 0; nf < 16; nf++)
        #pragma unroll
        for (int c = 0; c < 4; c++) oacc[nf][c] = 0.f;

    const char* QsB = sm + F2_QS_OFF;

    for (int t = 0; t < nt; t++) {
        const int st = t & 1;
        if (t + 1 < nt) { issueKV(t + 1, st ^ 1); cp_commit(); cp_wait<1>(); }
        else            { cp_wait<0>(); }
        __syncthreads();

        // ---- S = Q K^T : 16 rows x 32 keys per warp ----
        const char* KsB = sm + F2_KS_OFF + st * F2_KS_BYTES;
        float sacc[4][4];
        #pragma unroll
        for (int nf = 0; nf < 4; nf++)
            #pragma unroll
            for (int c = 0; c < 4; c++) sacc[nf][c] = 0.f;

        #pragma unroll 4
        for (int kk = 0; kk < 12; kk++) {
            uint2 qlo = *reinterpret_cast<const uint2*>(
                QsB + (r0 * F2_QS_STR + kk * 16 + 4 * tg) * 2);
            uint2 qhi = *reinterpret_cast<const uint2*>(
                QsB + ((r0 + 8) * F2_QS_STR + kk * 16 + 4 * tg) * 2);
            #pragma unroll
            for (int nf = 0; nf < 4; nf++) {
                uint2 bb = *reinterpret_cast<const uint2*>(
                    KsB + ((nf * 8 + gl) * F2_KS_STR + kk * 16 + 4 * tg) * 2);
                mma16(sacc[nf], qlo.x, qhi.x, qlo.y, qhi.y, bb.x, bb.y);
            }
        }

        // ---- in-register online softmax ----
        const bool msk = (t >= 2 * qt);
        float mx0 = -1e30f, mx1 = -1e30f;
        #pragma unroll
        for (int nf = 0; nf < 4; nf++) {
            #pragma unroll
            for (int c = 0; c < 4; c++) {
                float val = sacc[nf][c] * SCALE_;
                if (msk) {
                    int key = t * 32 + nf * 8 + 2 * tg + (c & 1);
                    int row = q0 + r0 + ((c & 2) ? 8 : 0);
                    if (key > row) val = -1e30f;
                }
                sacc[nf][c] = val;
                if (c & 2) mx1 = fmaxf(mx1, val); else mx0 = fmaxf(mx0, val);
            }
        }
        mx0 = fmaxf(mx0, __shfl_xor_sync(0xffffffffu, mx0, 1));
        mx0 = fmaxf(mx0, __shfl_xor_sync(0xffffffffu, mx0, 2));
        mx1 = fmaxf(mx1, __shfl_xor_sync(0xffffffffu, mx1, 1));
        mx1 = fmaxf(mx1, __shfl_xor_sync(0xffffffffu, mx1, 2));

        float mn0 = fmaxf(m0, mx0), mn1 = fmaxf(m1, mx1);
        float al0 = __expf(m0 - mn0), al1 = __expf(m1 - mn1);
        m0 = mn0; m1 = mn1;

        float s0 = 0.f, s1 = 0.f;
        uint32_t pa[4][2];
        #pragma unroll
        for (int nf = 0; nf < 4; nf++) {
            float e0 = __expf(sacc[nf][0] - mn0);
            float e1 = __expf(sacc[nf][1] - mn0);
            float e2 = __expf(sacc[nf][2] - mn1);
            float e3 = __expf(sacc[nf][3] - mn1);
            s0 += e0 + e1; s1 += e2 + e3;
            pa[nf][0] = pack_h2(e0, e1);
            pa[nf][1] = pack_h2(e2, e3);
        }
        s0 += __shfl_xor_sync(0xffffffffu, s0, 1);
        s0 += __shfl_xor_sync(0xffffffffu, s0, 2);
        s1 += __shfl_xor_sync(0xffffffffu, s1, 1);
        s1 += __shfl_xor_sync(0xffffffffu, s1, 2);
        l0 = l0 * al0 + s0;
        l1 = l1 * al1 + s1;

        // ---- rescale O, then O += P V ----
        #pragma unroll
        for (int nf = 0; nf < 16; nf++) {
            oacc[nf][0] *= al0; oacc[nf][1] *= al0;
            oacc[nf][2] *= al1; oacc[nf][3] *= al1;
        }
        const char* VsB = sm + F2_VS_OFF + st * F2_VS_BYTES;
        #pragma unroll
        for (int kk2 = 0; kk2 < 2; kk2++) {
            uint32_t a0 = pa[2 * kk2][0];
            uint32_t a1 = pa[2 * kk2][1];
            uint32_t a2 = pa[2 * kk2 + 1][0];
            uint32_t a3 = pa[2 * kk2 + 1][1];
            #pragma unroll
            for (int nf = 0; nf < 16; nf++) {
                uint2 bv = *reinterpret_cast<const uint2*>(
                    VsB + ((nf * 8 + gl) * F2_VS_STR + kk2 * 16 + 4 * tg) * 2);
                mma16(oacc[nf], a0, a1, a2, a3, bv.x, bv.y);
            }
        }
        __syncthreads();
    }

    // ---- epilogue: O / l ----
    float inv0 = 1.f / l0, inv1 = 1.f / l1;
    #pragma unroll
    for (int nf = 0; nf < 16; nf++) {
        int col = h * D_V + nf * 8 + 2 * tg;
        __half2* o0 = reinterpret_cast<__half2*>(attn + (size_t)(q0 + r0) * (H_ * D_V) + col);
        __half2* o8 = reinterpret_cast<__half2*>(attn + (size_t)(q0 + r0 + 8) * (H_ * D_V) + col);
        *o0 = __floats2half2_rn(oacc[nf][0] * inv0, oacc[nf][1] * inv0);
        *o8 = __floats2half2_rn(oacc[nf][2] * inv1, oacc[nf][3] * inv1);
    }
}

// ---------------- host launch ----------------
extern "C" void kernel_launch(void* const* d_in, const int* in_sizes, int n_in,
                              void* d_out, int out_size)
{
    const float* x       = (const float*)d_in[0];
    const int*   pos     = (const int*)  d_in[2];
    const float* cosT    = (const float*)d_in[3];
    const float* sinT    = (const float*)d_in[4];
    const float* q_a_w   = (const float*)d_in[5];
    const float* q_a_ln  = (const float*)d_in[6];
    const float* q_b_w   = (const float*)d_in[7];
    const float* kv_a_w  = (const float*)d_in[8];
    const float* kv_a_ln = (const float*)d_in[9];
    const float* kv_b_w  = (const float*)d_in[10];
    const float* o_w     = (const float*)d_in[11];
    float* out = (float*)d_out;
    float* out_cache = out + (size_t)S_ * HID_;

    __half *xc, *wqa, *wqb, *wkva, *wkvb, *wo, *qa, *qn, *cnorm, *q, *kv, *Q, *K, *V, *attn;
    float *ckv, *kpe;
    cudaGetSymbolAddress((void**)&xc,     g_x);
    cudaGetSymbolAddress((void**)&wqa,    g_wqa);
    cudaGetSymbolAddress((void**)&wqb,    g_wqb);
    cudaGetSymbolAddress((void**)&wkva,   g_wkva);
    cudaGetSymbolAddress((void**)&wkvb,   g_wkvb);
    cudaGetSymbolAddress((void**)&wo,     g_wo);
    cudaGetSymbolAddress((void**)&qa,     g_qa);
    cudaGetSymbolAddress((void**)&qn,     g_qn);
    cudaGetSymbolAddress((void**)&ckv,    g_ckv);
    cudaGetSymbolAddress((void**)&cnorm,  g_cnorm);
    cudaGetSymbolAddress((void**)&kpe,    g_kpe);
    cudaGetSymbolAddress((void**)&q,      g_q);
    cudaGetSymbolAddress((void**)&kv,     g_kv);
    cudaGetSymbolAddress((void**)&Q,      g_Q);
    cudaGetSymbolAddress((void**)&K,      g_K);
    cudaGetSymbolAddress((void**)&V,      g_V);
    cudaGetSymbolAddress((void**)&attn,   g_attn);

    cudaFuncSetAttribute(pgemm_kernel,  cudaFuncAttributeMaxDynamicSharedMemorySize, SMEM_P);
    cudaFuncSetAttribute(flash2_kernel, cudaFuncAttributeMaxDynamicSharedMemorySize, FLASH2_SMEM);

    // prep: all conversions in 1 launch
    {
        int n0 = S_ * HID_ / 4, n1 = HID_ * QL_ / 4, n2 = QL_ * QDIM / 4,
            n3 = KVL_ * KVDIM / 4, n4 = H_ * D_V * HID_ / 4,
            n5 = HID_ * KVA_PAD / 4;
        int total = n0 + n1 + n2 + n3 + n4 + n5;
        conv_multi_kernel<<<(total + 255) / 256, 256>>>(
            (const float4*)x,      (__half2*)xc,   n0,
            (const float4*)q_a_w,  (__half2*)wqa,  n1,
            (const float4*)q_b_w,  (__half2*)wqb,  n2,
            (const float4*)kv_b_w, (__half2*)wkvb, n3,
            (const float4*)o_w,    (__half2*)wo,   n4,
            kv_a_w, wkva, n5);
    }

    dim3 blk5(512);

    // 1) fused: qa(half) = x@q_a_w ; ckv(float) = x@kv_a_w (padded)
    pgemm_kernel<<<dim3(9, S_/128), blk5, SMEM_P>>>(
        xc, HID_, HID_, wqa, QL_, qa, QL_, QL_, 1, 6,
        xc, HID_, HID_, wkva, KVA_PAD, ckv, CKV_W, CKV_W, 0);
    // 2) fused RMSNorms
    rms_fused_kernel<<<dim3(S_, 2), 256>>>(qa, q_a_ln, ckv, kv_a_ln, cosT, sinT, pos,
                                           qn, cnorm, kpe, out_cache);
    // 3) fused: q(half) = qn@q_b_w ; kv(half) = cnorm@kv_b_w
    pgemm_kernel<<<dim3(28, S_/128), blk5, SMEM_P>>>(
        qn, QL_, QL_, wqb, QDIM, q, QDIM, QDIM, 1, 12,
        cnorm, KVL_, KVL_, wkvb, KVDIM, kv, KVDIM, KVDIM, 1);
    // 4) fused assemble Q/K + V transpose
    assemble_fused_kernel<<<dim3(S_/64, H_), 256>>>(q, kv, kpe, cosT, sinT, pos, Q, K, V);
    // 5) FA2 flash, 64-row q tiles, 3 CTAs/SM (proven round-12 shape)
    flash2_kernel<<<dim3(S_/64, H_), 128, FLASH2_SMEM>>>(Q, K, V, attn);
    // 6) out(float) = attn @ o_w
    pgemm_kernel<<<dim3(HID_/256, S_/128), blk5, SMEM_P>>>(
        attn, H_*D_V, H_*D_V, wo, HID_, out, HID_, HID_, 0, HID_/256,
        nullptr, 0, 0, nullptr, 0, nullptr, 0, 0, 0);
}

// round 16
// speedup vs baseline: 1.1859x; 1.0066x over previous
#include <cuda_runtime.h>
#include <cuda_fp16.h>
#include <mma.h>
#include <math.h>
#include <stdint.h>

using namespace nvcuda;

// ---------------- problem constants ----------------
#define S_      2048
#define HID_    2048
#define H_      16
#define D_NOPE  128
#define D_ROPE  64
#define D_V     128
#define QHEAD   192
#define QL_     1536
#define KVL_    512
#define CKV_W   576
#define KVA_PAD 768
#define QDIM    3072
#define KVDIM   4096
#define EPS_    1e-6f
#define SCALE_  0.07216878364870322f

// ---------------- scratch ----------------
__device__ __half g_x     [S_ * HID_];
__device__ __half g_wqa   [HID_ * QL_];
__device__ __half g_wqb   [QL_ * QDIM];
__device__ __half g_wkva  [HID_ * KVA_PAD];
__device__ __half g_wkvb  [KVL_ * KVDIM];
__device__ __half g_wo    [H_ * D_V * HID_];
__device__ __half g_qa    [S_ * QL_];
__device__ __half g_qn    [S_ * QL_];
__device__ float  g_ckv   [S_ * CKV_W];
__device__ __half g_cnorm [S_ * KVL_];
__device__ float  g_kpe   [S_ * D_ROPE];
__device__ __half g_q     [S_ * QDIM];
__device__ __half g_kv    [S_ * KVDIM];
__device__ __half g_Q     [H_ * S_ * QHEAD];
__device__ __half g_K     [H_ * S_ * QHEAD];
__device__ __half g_V     [H_ * D_V * S_];
__device__ __half g_attn  [S_ * (H_ * D_V)];
// split-KV partials: [part 0..3][h][row][128]
__device__ float  g_pO    [4 * H_ * S_ * D_V];
__device__ float  g_pm    [4 * H_ * S_];
__device__ float  g_pl    [4 * H_ * S_];

__device__ __forceinline__ int perm16(int c) {
    int j = c & 15;
    return (c & ~15) | (((j >> 1) & 3) << 2) | ((j >> 3) << 1) | (j & 1);
}
__device__ __forceinline__ uint32_t smem_u32(const void* p) {
    uint32_t a;
    asm("{ .reg .u64 t; cvta.to.shared.u64 t, %1; cvt.u32.u64 %0, t; }" : "=r"(a) : "l"(p));
    return a;
}
__device__ __forceinline__ void cp16(uint32_t d, const void* s) {
    asm volatile("cp.async.ca.shared.global [%0], [%1], 16;" :: "r"(d), "l"(s));
}
__device__ __forceinline__ void cp_commit() {
    asm volatile("cp.async.commit_group;" ::: "memory");
}
template<int N> __device__ __forceinline__ void cp_wait() {
    asm volatile("cp.async.wait_group %0;" :: "n"(N) : "memory");
}
__device__ __forceinline__ void mma16(float* c, uint32_t a0, uint32_t a1, uint32_t a2, uint32_t a3,
                                      uint32_t b0, uint32_t b1) {
    asm volatile(
        "mma.sync.aligned.m16n8k16.row.col.f32.f16.f16.f32 "
        "{%0,%1,%2,%3}, {%4,%5,%6,%7}, {%8,%9}, {%0,%1,%2,%3};"
        : "+f"(c[0]), "+f"(c[1]), "+f"(c[2]), "+f"(c[3])
        : "r"(a0), "r"(a1), "r"(a2), "r"(a3), "r"(b0), "r"(b1));
}
__device__ __forceinline__ uint32_t pack_h2(float lo, float hi) {
    __half2 p = __floats2half2_rn(lo, hi);
    return *reinterpret_cast<uint32_t*>(&p);
}

// ---------------- prep: fused fp16 conversion ----------------
__global__ void conv_multi_kernel(
    const float4* __restrict__ s0, __half2* __restrict__ d0, int n0,
    const float4* __restrict__ s1, __half2* __restrict__ d1, int n1,
    const float4* __restrict__ s2, __half2* __restrict__ d2, int n2,
    const float4* __restrict__ s3, __half2* __restrict__ d3, int n3,
    const float4* __restrict__ s4, __half2* __restrict__ d4, int n4,
    const float* __restrict__ kva, __half* __restrict__ wkva, int n5)
{
    int i = blockIdx.x * blockDim.x + threadIdx.x;
    int j = i;
    if (j < n0) {
        float4 v = s0[j];
        d0[2*j+0] = __floats2half2_rn(v.x, v.y); d0[2*j+1] = __floats2half2_rn(v.z, v.w);
        return;
    }
    j -= n0;
    if (j < n1) {
        float4 v = s1[j];
        d1[2*j+0] = __floats2half2_rn(v.x, v.y); d1[2*j+1] = __floats2half2_rn(v.z, v.w);
        return;
    }
    j -= n1;
    if (j < n2) {
        float4 v = s2[j];
        d2[2*j+0] = __floats2half2_rn(v.x, v.y); d2[2*j+1] = __floats2half2_rn(v.z, v.w);
        return;
    }
    j -= n2;
    if (j < n3) {
        float4 v = s3[j];
        d3[2*j+0] = __floats2half2_rn(v.x, v.y); d3[2*j+1] = __floats2half2_rn(v.z, v.w);
        return;
    }
    j -= n3;
    if (j < n4) {
        float4 v = s4[j];
        d4[2*j+0] = __floats2half2_rn(v.x, v.y); d4[2*j+1] = __floats2half2_rn(v.z, v.w);
        return;
    }
    j -= n4;
    if (j < n5) {
        int k = (4 * j) / KVA_PAD, n = (4 * j) % KVA_PAD;
        __half2 lo, hi;
        if (n < CKV_W) {
            float4 v = *reinterpret_cast<const float4*>(kva + (size_t)k * CKV_W + n);
            lo = __floats2half2_rn(v.x, v.y); hi = __floats2half2_rn(v.z, v.w);
        } else {
            lo = __floats2half2_rn(0.f, 0.f); hi = lo;
        }
        __half2* dp = reinterpret_cast<__half2*>(wkva + (size_t)k * KVA_PAD + n);
        dp[0] = lo; dp[1] = hi;
    }
}

// ---------------- pipelined fp16 GEMM, dual problem sets, optional half output ----------------
#define A_STRH 72
#define B_STRH 264
#define A_SBYT (128 * A_STRH * 2)
#define B_SBYT (64 * B_STRH * 2)
#define STG_P  (A_SBYT + B_SBYT)
#define SMEM_P (3 * STG_P)

__global__ __launch_bounds__(512, 1)
void pgemm_kernel(const __half* __restrict__ A, int lda, int K,
                  const __half* __restrict__ B, int ldb,
                  void* __restrict__ C, int ldc, int N, int ho, int nt1,
                  const __half* __restrict__ A2, int lda2, int K2,
                  const __half* __restrict__ B2, int ldb2,
                  void* __restrict__ C2, int ldc2, int N2, int ho2)
{
    int bx = blockIdx.x;
    if (bx >= nt1) {
        A = A2; lda = lda2; K = K2; B = B2; ldb = ldb2;
        C = C2; ldc = ldc2; N = N2; ho = ho2;
        bx -= nt1;
    }
    const int row0 = blockIdx.y * 128;
    const int col0 = bx * 256;
    const int nk = K / 64;

    extern __shared__ char smem[];
    const uint32_t sb = smem_u32(smem);
    const int tid = threadIdx.x;
    const int wid = tid >> 5;
    const int wm  = wid >> 3;
    const int wn  = wid & 7;

    auto issue = [&](int t) {
        const int s = t % 3;
        const int k0 = t * 64;
        uint32_t ab = sb + s * STG_P;
        #pragma unroll
        for (int i = 0; i < 2; i++) {
            int idx = i * 512 + tid;
            int r = idx >> 3, c = idx & 7;
            cp16(ab + r * (A_STRH * 2) + c * 16, A + (size_t)(row0 + r) * lda + k0 + c * 8);
        }
        uint32_t bb = sb + s * STG_P + A_SBYT;
        #pragma unroll
        for (int i = 0; i < 4; i++) {
            int idx = i * 512 + tid;
            int kr = idx >> 5, c = idx & 31;
            cp16(bb + kr * (B_STRH * 2) + c * 16, B + (size_t)(k0 + kr) * ldb + col0 + c * 8);
        }
    };

    typedef wmma::fragment<wmma::matrix_a, 16, 16, 16, __half, wmma::row_major> AFrag;
    typedef wmma::fragment<wmma::matrix_b, 16, 16, 16, __half, wmma::row_major> BFrag;
    wmma::fragment<wmma::accumulator, 16, 16, 16, float> acc[4][2];
    #pragma unroll
    for (int i = 0; i < 4; i++)
        #pragma unroll
        for (int j = 0; j < 2; j++) wmma::fill_fragment(acc[i][j], 0.0f);

    issue(0); cp_commit();
    if (nk > 1) { issue(1); cp_commit(); }

    for (int t = 0; t < nk; t++) {
        if (t + 1 < nk) cp_wait<1>(); else cp_wait<0>();
        __syncthreads();
        if (t + 2 < nk) { issue(t + 2); cp_commit(); }

        const __half* As = reinterpret_cast<const __half*>(smem + (t % 3) * STG_P);
        const __half* Bs = reinterpret_cast<const __half*>(smem + (t % 3) * STG_P + A_SBYT);

        #pragma unroll
        for (int kk = 0; kk < 4; kk++) {
            AFrag af[4];
            BFrag bf[2];
            #pragma unroll
            for (int mf = 0; mf < 4; mf++)
                wmma::load_matrix_sync(af[mf], As + (wm * 64 + mf * 16) * A_STRH + kk * 16, A_STRH);
            #pragma unroll
            for (int nf = 0; nf < 2; nf++)
                wmma::load_matrix_sync(bf[nf], Bs + (kk * 16) * B_STRH + wn * 32 + nf * 16, B_STRH);
            #pragma unroll
            for (int mf = 0; mf < 4; mf++)
                #pragma unroll
                for (int nf = 0; nf < 2; nf++)
                    wmma::mma_sync(acc[mf][nf], af[mf], bf[nf], acc[mf][nf]);
        }
    }

    if (ho) {
        __half* Ch = reinterpret_cast<__half*>(C);
        #pragma unroll
        for (int mf = 0; mf < 4; mf++) {
            int gr = row0 + wm * 64 + mf * 16;
            #pragma unroll
            for (int nf = 0; nf < 2; nf++) {
                int gc = col0 + wn * 32 + nf * 16;
                if (gc + 16 <= N) {
                    wmma::fragment<wmma::accumulator, 16, 16, 16, __half> hacc;
                    #pragma unroll
                    for (int e = 0; e < hacc.num_elements; e++)
                        hacc.x[e] = __float2half(acc[mf][nf].x[e]);
                    wmma::store_matrix_sync(Ch + (size_t)gr * ldc + gc, hacc, ldc,
                                            wmma::mem_row_major);
                }
            }
        }
    } else {
        float* Cf = reinterpret_cast<float*>(C);
        #pragma unroll
        for (int mf = 0; mf < 4; mf++) {
            int gr = row0 + wm * 64 + mf * 16;
            #pragma unroll
            for (int nf = 0; nf < 2; nf++) {
                int gc = col0 + wn * 32 + nf * 16;
                if (gc + 16 <= N)
                    wmma::store_matrix_sync(Cf + (size_t)gr * ldc + gc, acc[mf][nf], ldc,
                                            wmma::mem_row_major);
            }
        }
    }
}

// ---------------- fused RMSNorm: grid.y 0 -> q_a(half), 1 -> ckv(float) ----------------
__global__ __launch_bounds__(256)
void rms_fused_kernel(const __half* __restrict__ qa, const float* __restrict__ wq,
                      const float* __restrict__ ckv, const float* __restrict__ wkv,
                      const float* __restrict__ cosT, const float* __restrict__ sinT,
                      const int* __restrict__ pos,
                      __half* __restrict__ qn, __half* __restrict__ cnorm,
                      float* __restrict__ kpe, float* __restrict__ cache)
{
    const int s = blockIdx.x;
    const int tid = threadIdx.x;
    __shared__ float sred[256];

    if (blockIdx.y == 0) {
        const __half* x = qa + (size_t)s * QL_;
        __half*       y = qn + (size_t)s * QL_;
        float v[6];
        float local = 0.f;
        #pragma unroll
        for (int i = 0; i < 6; i++) { int c = tid + i * 256; v[i] = __half2float(x[c]); local += v[i] * v[i]; }
        sred[tid] = local; __syncthreads();
        for (int st = 128; st > 0; st >>= 1) {
            if (tid < st) sred[tid] += sred[tid + st];
            __syncthreads();
        }
        float scale = rsqrtf(sred[0] / (float)QL_ + EPS_);
        #pragma unroll
        for (int i = 0; i < 6; i++) { int c = tid + i * 256; y[c] = __float2half(v[i] * scale * wq[c]); }
    } else {
        const float* x = ckv + (size_t)s * CKV_W;
        float v[2];
        float local = 0.f;
        #pragma unroll
        for (int i = 0; i < 2; i++) { int c = tid + i * 256; v[i] = x[c]; local += v[i] * v[i]; }
        sred[tid] = local; __syncthreads();
        for (int st = 128; st > 0; st >>= 1) {
            if (tid < st) sred[tid] += sred[tid + st];
            __syncthreads();
        }
        float scale = rsqrtf(sred[0] / (float)KVL_ + EPS_);
        #pragma unroll
        for (int i = 0; i < 2; i++) {
            int c = tid + i * 256;
            float y = v[i] * scale * wkv[c];
            cnorm[(size_t)s * KVL_ + c] = __float2half(y);
            cache[(size_t)s * CKV_W + c] = y;
        }
        if (tid < D_ROPE) {
            int p = pos[s];
            const float* cr = cosT + (size_t)p * D_ROPE;
            const float* sr = sinT + (size_t)p * D_ROPE;
            const float* t  = x + KVL_;
            int i = tid;
            float val;
            if (i < 32) val = t[2 * i] * cr[i] - t[2 * i + 1] * sr[i];
            else { int i2 = i - 32; val = t[2 * i2 + 1] * cr[i] + t[2 * i2] * sr[i]; }
            kpe[(size_t)s * D_ROPE + i] = val;
            cache[(size_t)s * CKV_W + KVL_ + i] = val;
        }
    }
}

// ---------------- fused assemble Q/K (perm16) + V transpose (half inputs) ----------------
__global__ __launch_bounds__(256)
void assemble_fused_kernel(const __half* __restrict__ q, const __half* __restrict__ kv,
                           const float* __restrict__ kpe,
                           const float* __restrict__ cosT, const float* __restrict__ sinT,
                           const int* __restrict__ pos,
                           __half* __restrict__ Q, __half* __restrict__ K,
                           __half* __restrict__ V)
{
    const int s0 = blockIdx.x * 64;
    const int h  = blockIdx.y;
    const int tid = threadIdx.x;

    #pragma unroll
    for (int it = 0; it < 48; it++) {
        int idx = it * 256 + tid;
        int sl = idx / QHEAD, d = idx % QHEAD;
        int s = s0 + sl;
        const __half* qrow  = q  + (size_t)s * QDIM  + h * QHEAD;
        const __half* kvrow = kv + (size_t)s * KVDIM + h * (D_NOPE + D_V);
        const size_t off = ((size_t)h * S_ + s) * QHEAD;

        float qv;
        if (d < D_NOPE) qv = __half2float(qrow[d]);
        else {
            int p = pos[s];
            const float* cr = cosT + (size_t)p * D_ROPE;
            const float* sr = sinT + (size_t)p * D_ROPE;
            const __half* t = qrow + D_NOPE;
            int i = d - D_NOPE;
            if (i < 32) qv = __half2float(t[2 * i]) * cr[i] - __half2float(t[2 * i + 1]) * sr[i];
            else { int i2 = i - 32; qv = __half2float(t[2 * i2 + 1]) * cr[i] + __half2float(t[2 * i2]) * sr[i]; }
        }
        float kvv = (d < D_NOPE) ? __half2float(kvrow[d]) : kpe[(size_t)s * D_ROPE + (d - D_NOPE)];
        int pd = perm16(d);
        Q[off + pd] = __float2half(qv);
        K[off + pd] = __float2half(kvv);
    }

    __shared__ __half vt[64 * 136];
    #pragma unroll
    for (int i = 0; i < 32; i++) {
        int idx = i * 256 + tid;
        int sl = idx >> 7, d = idx & 127;
        vt[sl * 136 + d] = kv[(size_t)(s0 + sl) * KVDIM + h * (D_NOPE + D_V) + D_NOPE + d];
    }
    __syncthreads();
    #pragma unroll
    for (int i = 0; i < 32; i++) {
        int idx = i * 256 + tid;
        int d = idx >> 6, sl = idx & 63;
        V[((size_t)h * D_V + d) * S_ + s0 + perm16(sl)] = vt[sl * 136 + d];
    }
}

// ---------------- split-KV FA2 flash: parts of <=16 key-tiles, unnormalized output ----------------
#define F2_QS_STR 200
#define F2_KS_STR 200
#define F2_VS_STR 40
#define F2_QS_OFF 0
#define F2_KS_OFF 25600
#define F2_KS_BYTES 12800
#define F2_VS_OFF (F2_KS_OFF + 2*F2_KS_BYTES)
#define F2_VS_BYTES 10240
#define FLASH2_SMEM (F2_VS_OFF + 2*F2_VS_BYTES)

__global__ __launch_bounds__(128, 3)
void flash_split_kernel(const __half* __restrict__ Q, const __half* __restrict__ K,
                        const __half* __restrict__ V,
                        float* __restrict__ pO, float* __restrict__ pm, float* __restrict__ pl)
{
    // bx 0..79 -> (qt, part)
    const int bx = blockIdx.x;
    int qt, prt;
    if (bx < 8)       { qt = bx;             prt = 0; }
    else if (bx < 24) { qt = 8 + (bx-8)/2;   prt = (bx-8)&1; }
    else if (bx < 48) { qt = 16 + (bx-24)/3; prt = (bx-24)%3; }
    else              { qt = 24 + (bx-48)/4; prt = (bx-48)&3; }
    const int h  = blockIdx.y;
    const int q0 = qt * 64;
    const int nt = 2 * qt + 2;
    const int t0 = prt * 16;
    const int t1 = min(nt, t0 + 16);

    extern __shared__ char sm[];
    const uint32_t sb = smem_u32(sm);

    const int tid = threadIdx.x;
    const int wid = tid >> 5;
    const int lid = tid & 31;
    const int gl  = lid >> 2;
    const int tg  = lid & 3;
    const int r0  = wid * 16 + gl;

    const __half* Qg = Q + ((size_t)h * S_ + q0) * QHEAD;
    const __half* Kg = K + (size_t)h * S_ * QHEAD;
    const __half* Vg = V + (size_t)h * D_V * S_;

    auto issueKV = [&](int t, int st) {
        const __half* kp = Kg + (size_t)t * 32 * QHEAD;
        uint32_t kd = sb + F2_KS_OFF + st * F2_KS_BYTES;
        #pragma unroll
        for (int i = 0; i < 6; i++) {
            int idx = i * 128 + tid;
            int r = idx / 24, c = idx % 24;
            cp16(kd + r * (F2_KS_STR * 2) + c * 16, kp + (size_t)r * QHEAD + c * 8);
        }
        uint32_t vd = sb + F2_VS_OFF + st * F2_VS_BYTES;
        #pragma unroll
        for (int i = 0; i < 4; i++) {
            int idx = i * 128 + tid;
            int d = idx >> 2, c = idx & 3;
            cp16(vd + d * (F2_VS_STR * 2) + c * 16, Vg + (size_t)d * S_ + t * 32 + c * 8);
        }
    };

    #pragma unroll
    for (int i = 0; i < 12; i++) {
        int idx = i * 128 + tid;
        int r = idx / 24, c = idx % 24;
        cp16(sb + F2_QS_OFF + r * (F2_QS_STR * 2) + c * 16, Qg + (size_t)r * QHEAD + c * 8);
    }
    issueKV(t0, t0 & 1);
    cp_commit();

    float m0 = -1e30f, m1 = -1e30f, l0 = 0.f, l1 = 0.f;
    float oacc[16][4];
    #pragma unroll
    for (int nf = 0; nf < 16; nf++)
        #pragma unroll
        for (int c = 0; c < 4; c++) oacc[nf][c] = 0.f;

    const char* QsB = sm + F2_QS_OFF;

    for (int t = t0; t < t1; t++) {
        const int st = t & 1;
        if (t + 1 < t1) { issueKV(t + 1, st ^ 1); cp_commit(); cp_wait<1>(); }
        else            { cp_wait<0>(); }
        __syncthreads();

        const char* KsB = sm + F2_KS_OFF + st * F2_KS_BYTES;
        float sacc[4][4];
        #pragma unroll
        for (int nf = 0; nf < 4; nf++)
            #pragma unroll
            for (int c = 0; c < 4; c++) sacc[nf][c] = 0.f;

        #pragma unroll 4
        for (int kk = 0; kk < 12; kk++) {
            uint2 qlo = *reinterpret_cast<const uint2*>(
                QsB + (r0 * F2_QS_STR + kk * 16 + 4 * tg) * 2);
            uint2 qhi = *reinterpret_cast<const uint2*>(
                QsB + ((r0 + 8) * F2_QS_STR + kk * 16 + 4 * tg) * 2);
            #pragma unroll
            for (int nf = 0; nf < 4; nf++) {
                uint2 bb = *reinterpret_cast<const uint2*>(
                    KsB + ((nf * 8 + gl) * F2_KS_STR + kk * 16 + 4 * tg) * 2);
                mma16(sacc[nf], qlo.x, qhi.x, qlo.y, qhi.y, bb.x, bb.y);
            }
        }

        const bool msk = (t >= 2 * qt);
        float mx0 = -1e30f, mx1 = -1e30f;
        #pragma unroll
        for (int nf = 0; nf < 4; nf++) {
            #pragma unroll
            for (int c = 0; c < 4; c++) {
                float val = sacc[nf][c] * SCALE_;
                if (msk) {
                    int key = t * 32 + nf * 8 + 2 * tg + (c & 1);
                    int row = q0 + r0 + ((c & 2) ? 8 : 0);
                    if (key > row) val = -1e30f;
                }
                sacc[nf][c] = val;
                if (c & 2) mx1 = fmaxf(mx1, val); else mx0 = fmaxf(mx0, val);
            }
        }
        mx0 = fmaxf(mx0, __shfl_xor_sync(0xffffffffu, mx0, 1));
        mx0 = fmaxf(mx0, __shfl_xor_sync(0xffffffffu, mx0, 2));
        mx1 = fmaxf(mx1, __shfl_xor_sync(0xffffffffu, mx1, 1));
        mx1 = fmaxf(mx1, __shfl_xor_sync(0xffffffffu, mx1, 2));

        float mn0 = fmaxf(m0, mx0), mn1 = fmaxf(m1, mx1);
        float al0 = __expf(m0 - mn0), al1 = __expf(m1 - mn1);
        m0 = mn0; m1 = mn1;

        float s0 = 0.f, s1 = 0.f;
        uint32_t pa[4][2];
        #pragma unroll
        for (int nf = 0; nf < 4; nf++) {
            float e0 = __expf(sacc[nf][0] - mn0);
            float e1 = __expf(sacc[nf][1] - mn0);
            float e2 = __expf(sacc[nf][2] - mn1);
            float e3 = __expf(sacc[nf][3] - mn1);
            s0 += e0 + e1; s1 += e2 + e3;
            pa[nf][0] = pack_h2(e0, e1);
            pa[nf][1] = pack_h2(e2, e3);
        }
        s0 += __shfl_xor_sync(0xffffffffu, s0, 1);
        s0 += __shfl_xor_sync(0xffffffffu, s0, 2);
        s1 += __shfl_xor_sync(0xffffffffu, s1, 1);
        s1 += __shfl_xor_sync(0xffffffffu, s1, 2);
        l0 = l0 * al0 + s0;
        l1 = l1 * al1 + s1;

        #pragma unroll
        for (int nf = 0; nf < 16; nf++) {
            oacc[nf][0] *= al0; oacc[nf][1] *= al0;
            oacc[nf][2] *= al1; oacc[nf][3] *= al1;
        }
        const char* VsB = sm + F2_VS_OFF + st * F2_VS_BYTES;
        #pragma unroll
        for (int kk2 = 0; kk2 < 2; kk2++) {
            uint32_t a0 = pa[2 * kk2][0];
            uint32_t a1 = pa[2 * kk2][1];
            uint32_t a2 = pa[2 * kk2 + 1][0];
            uint32_t a3 = pa[2 * kk2 + 1][1];
            #pragma unroll
            for (int nf = 0; nf < 16; nf++) {
                uint2 bv = *reinterpret_cast<const uint2*>(
                    VsB + ((nf * 8 + gl) * F2_VS_STR + kk2 * 16 + 4 * tg) * 2);
                mma16(oacc[nf], a0, a1, a2, a3, bv.x, bv.y);
            }
        }
        __syncthreads();
    }

    // ---- write unnormalized partials ----
    const size_t base0 = (((size_t)prt * H_ + h) * S_ + (q0 + r0)) * D_V;
    const size_t base8 = base0 + 8 * D_V;
    #pragma unroll
    for (int nf = 0; nf < 16; nf++) {
        int col = nf * 8 + 2 * tg;
        *reinterpret_cast<float2*>(pO + base0 + col) = make_float2(oacc[nf][0], oacc[nf][1]);
        *reinterpret_cast<float2*>(pO + base8 + col) = make_float2(oacc[nf][2], oacc[nf][3]);
    }
    if (tg == 0) {
        size_t mi = ((size_t)prt * H_ + h) * S_ + (q0 + r0);
        pm[mi] = m0;  pl[mi] = l0;
        pm[mi + 8] = m1;  pl[mi + 8] = l1;
    }
}

// ---------------- merge partials -> attn (fp16) ----------------
// grid (S_/64, H_), 256 threads; thread: row_local = tid>>2, colgroup = tid&3 (32 cols)
__global__ __launch_bounds__(256)
void flash_merge_kernel(const float* __restrict__ pO, const float* __restrict__ pm,
                        const float* __restrict__ pl, __half* __restrict__ attn)
{
    const int qt = blockIdx.x;
    const int h  = blockIdx.y;
    const int nparts = (qt < 8) ? 1 : (qt < 16) ? 2 : (qt < 24) ? 3 : 4;
    const int tid = threadIdx.x;
    const int rl = tid >> 2;
    const int cg = (tid & 3) * 32;
    const int row = qt * 64 + rl;

    float mm[4], cf[4];
    float mstar = -1e30f;
    for (int p = 0; p < nparts; p++) {
        mm[p] = pm[((size_t)p * H_ + h) * S_ + row];
        mstar = fmaxf(mstar, mm[p]);
    }
    float lstar = 0.f;
    for (int p = 0; p < nparts; p++) {
        cf[p] = __expf(mm[p] - mstar);
        lstar += pl[((size_t)p * H_ + h) * S_ + row] * cf[p];
    }
    float inv = 1.f / lstar;

    __half* arow = attn + (size_t)row * (H_ * D_V) + h * D_V + cg;
    #pragma unroll
    for (int j = 0; j < 8; j++) {
        int c = cg + j * 4;
        float4 acc = make_float4(0.f, 0.f, 0.f, 0.f);
        for (int p = 0; p < nparts; p++) {
            float4 v = *reinterpret_cast<const float4*>(
                pO + (((size_t)p * H_ + h) * S_ + row) * D_V + c);
            acc.x += v.x * cf[p]; acc.y += v.y * cf[p];
            acc.z += v.z * cf[p]; acc.w += v.w * cf[p];
        }
        __half2* dst = reinterpret_cast<__half2*>(arow + j * 4);
        dst[0] = __floats2half2_rn(acc.x * inv, acc.y * inv);
        dst[1] = __floats2half2_rn(acc.z * inv, acc.w * inv);
    }
}

// ---------------- host launch ----------------
extern "C" void kernel_launch(void* const* d_in, const int* in_sizes, int n_in,
                              void* d_out, int out_size)
{
    const float* x       = (const float*)d_in[0];
    const int*   pos     = (const int*)  d_in[2];
    const float* cosT    = (const float*)d_in[3];
    const float* sinT    = (const float*)d_in[4];
    const float* q_a_w   = (const float*)d_in[5];
    const float* q_a_ln  = (const float*)d_in[6];
    const float* q_b_w   = (const float*)d_in[7];
    const float* kv_a_w  = (const float*)d_in[8];
    const float* kv_a_ln = (const float*)d_in[9];
    const float* kv_b_w  = (const float*)d_in[10];
    const float* o_w     = (const float*)d_in[11];
    float* out = (float*)d_out;
    float* out_cache = out + (size_t)S_ * HID_;

    __half *xc, *wqa, *wqb, *wkva, *wkvb, *wo, *qa, *qn, *cnorm, *q, *kv, *Q, *K, *V, *attn;
    float *ckv, *kpe, *pO, *pm, *pl;
    cudaGetSymbolAddress((void**)&xc,     g_x);
    cudaGetSymbolAddress((void**)&wqa,    g_wqa);
    cudaGetSymbolAddress((void**)&wqb,    g_wqb);
    cudaGetSymbolAddress((void**)&wkva,   g_wkva);
    cudaGetSymbolAddress((void**)&wkvb,   g_wkvb);
    cudaGetSymbolAddress((void**)&wo,     g_wo);
    cudaGetSymbolAddress((void**)&qa,     g_qa);
    cudaGetSymbolAddress((void**)&qn,     g_qn);
    cudaGetSymbolAddress((void**)&ckv,    g_ckv);
    cudaGetSymbolAddress((void**)&cnorm,  g_cnorm);
    cudaGetSymbolAddress((void**)&kpe,    g_kpe);
    cudaGetSymbolAddress((void**)&q,      g_q);
    cudaGetSymbolAddress((void**)&kv,     g_kv);
    cudaGetSymbolAddress((void**)&Q,      g_Q);
    cudaGetSymbolAddress((void**)&K,      g_K);
    cudaGetSymbolAddress((void**)&V,      g_V);
    cudaGetSymbolAddress((void**)&attn,   g_attn);
    cudaGetSymbolAddress((void**)&pO,     g_pO);
    cudaGetSymbolAddress((void**)&pm,     g_pm);
    cudaGetSymbolAddress((void**)&pl,     g_pl);

    cudaFuncSetAttribute(pgemm_kernel,       cudaFuncAttributeMaxDynamicSharedMemorySize, SMEM_P);
    cudaFuncSetAttribute(flash_split_kernel, cudaFuncAttributeMaxDynamicSharedMemorySize, FLASH2_SMEM);

    // prep: all conversions in 1 launch
    {
        int n0 = S_ * HID_ / 4, n1 = HID_ * QL_ / 4, n2 = QL_ * QDIM / 4,
            n3 = KVL_ * KVDIM / 4, n4 = H_ * D_V * HID_ / 4,
            n5 = HID_ * KVA_PAD / 4;
        int total = n0 + n1 + n2 + n3 + n4 + n5;
        conv_multi_kernel<<<(total + 255) / 256, 256>>>(
            (const float4*)x,      (__half2*)xc,   n0,
            (const float4*)q_a_w,  (__half2*)wqa,  n1,
            (const float4*)q_b_w,  (__half2*)wqb,  n2,
            (const float4*)kv_b_w, (__half2*)wkvb, n3,
            (const float4*)o_w,    (__half2*)wo,   n4,
            kv_a_w, wkva, n5);
    }

    dim3 blk5(512);

    // 1) fused: qa(half) = x@q_a_w ; ckv(float) = x@kv_a_w (padded)
    pgemm_kernel<<<dim3(9, S_/128), blk5, SMEM_P>>>(
        xc, HID_, HID_, wqa, QL_, qa, QL_, QL_, 1, 6,
        xc, HID_, HID_, wkva, KVA_PAD, ckv, CKV_W, CKV_W, 0);
    // 2) fused RMSNorms
    rms_fused_kernel<<<dim3(S_, 2), 256>>>(qa, q_a_ln, ckv, kv_a_ln, cosT, sinT, pos,
                                           qn, cnorm, kpe, out_cache);
    // 3) fused: q(half) = qn@q_b_w ; kv(half) = cnorm@kv_b_w
    pgemm_kernel<<<dim3(28, S_/128), blk5, SMEM_P>>>(
        qn, QL_, QL_, wqb, QDIM, q, QDIM, QDIM, 1, 12,
        cnorm, KVL_, KVL_, wkvb, KVDIM, kv, KVDIM, KVDIM, 1);
    // 4) fused assemble Q/K + V transpose
    assemble_fused_kernel<<<dim3(S_/64, H_), 256>>>(q, kv, kpe, cosT, sinT, pos, Q, K, V);
    // 5) split-KV flash (80 parts/head) + merge
    flash_split_kernel<<<dim3(80, H_), 128, FLASH2_SMEM>>>(Q, K, V, pO, pm, pl);
    flash_merge_kernel<<<dim3(S_/64, H_), 256>>>(pO, pm, pl, attn);
    // 6) out(float) = attn @ o_w
    pgemm_kernel<<<dim3(HID_/256, S_/128), blk5, SMEM_P>>>(
        attn, H_*D_V, H_*D_V, wo, HID_, out, HID_, HID_, 0, HID_/256,
        nullptr, 0, 0, nullptr, 0, nullptr, 0, 0, 0);
}